// round 1
// baseline (speedup 1.0000x reference)
#include <cuda_runtime.h>
#include <cuda_bf16.h>
#include <math.h>

#define BB    4
#define NPTS  8192
#define SPTS  2048
#define D1C   128
#define D2C   256
#define CIN   384
#define CMID  256
#define COUT  256
#define BNT   (BB*NPTS)   // 32768

// ---- scratch (device globals; no allocation allowed) ----
__device__ float g_f2t[BB*SPTS*D2C];     // feature2 transposed [B,S,D2]
__device__ float g_feat[CIN*BNT];        // concat input  [CIN, B*N]
__device__ float g_y1[CMID*BNT];         // conv1 pre-BN  [CMID, B*N]
__device__ int   g_idx[BNT*3];
__device__ float g_w[BNT*3];
__device__ float g_scale1[CMID], g_shift1[CMID];
__device__ float g_scale2[COUT], g_shift2[COUT];

// ============================================================
// 3-NN: for each point, 3 smallest squared distances (ref formula)
// ============================================================
__global__ void knn_kernel(const float* __restrict__ pos1,
                           const float* __restrict__ pos2) {
    __shared__ float sx[SPTS], sy[SPTS], sz[SPTS], sn[SPTS];
    int b = blockIdx.y;
    const float* p2 = pos2 + (size_t)b*3*SPTS;
    for (int s = threadIdx.x; s < SPTS; s += blockDim.x) {
        float x = p2[s], y = p2[SPTS+s], z = p2[2*SPTS+s];
        sx[s]=x; sy[s]=y; sz[s]=z; sn[s]=x*x+y*y+z*z;
    }
    __syncthreads();

    int n = blockIdx.x*blockDim.x + threadIdx.x;
    const float* p1 = pos1 + (size_t)b*3*NPTS;
    float px = p1[n], py = p1[NPTS+n], pz = p1[2*NPTS+n];
    float n1 = px*px+py*py+pz*pz;

    float d0v=1e30f, d1v=1e30f, d2v=1e30f;
    int   i0=0, i1=0, i2=0;
    #pragma unroll 4
    for (int s = 0; s < SPTS; s++) {
        float dot = px*sx[s] + py*sy[s] + pz*sz[s];
        float d = n1 - 2.0f*dot + sn[s];
        if (d < d2v) {
            if (d < d1v) {
                d2v = d1v; i2 = i1;
                if (d < d0v) { d1v = d0v; i1 = i0; d0v = d; i0 = s; }
                else         { d1v = d;   i1 = s; }
            } else { d2v = d; i2 = s; }
        }
    }
    float a0 = fmaxf(d0v, 1e-10f), a1 = fmaxf(d1v, 1e-10f), a2 = fmaxf(d2v, 1e-10f);
    float w0 = 1.0f/a0, w1 = 1.0f/a1, w2 = 1.0f/a2;
    float inv = 1.0f/(w0+w1+w2);
    int base = (b*NPTS + n)*3;
    g_idx[base+0]=i0; g_idx[base+1]=i1; g_idx[base+2]=i2;
    g_w[base+0]=w0*inv; g_w[base+1]=w1*inv; g_w[base+2]=w2*inv;
}

// ============================================================
// feature2 [B,D2,S] -> g_f2t [B,S,D2]
// ============================================================
__global__ void transpose_f2(const float* __restrict__ f2) {
    __shared__ float t[32][33];
    int b = blockIdx.z;
    int d0 = blockIdx.y*32, s0 = blockIdx.x*32;
    int lx = threadIdx.x, ly = threadIdx.y;
    const float* src = f2 + (size_t)b*D2C*SPTS;
    #pragma unroll
    for (int i = ly; i < 32; i += 8)
        t[i][lx] = src[(size_t)(d0+i)*SPTS + s0 + lx];
    __syncthreads();
    float* dst = g_f2t + (size_t)b*SPTS*D2C;
    #pragma unroll
    for (int i = ly; i < 32; i += 8)
        dst[(size_t)(s0+i)*D2C + d0 + lx] = t[lx][i];
}

// ============================================================
// weighted 3-NN interpolation -> g_feat rows [0, D2)
// block = 32 points x all 256 channels, transposed through shared
// ============================================================
__global__ void interp_kernel() {
    __shared__ float tile[32][33];
    __shared__ int   si[32*3];
    __shared__ float sw[32*3];
    int bn0 = blockIdx.x*32;
    int t = threadIdx.x;
    if (t < 96) { si[t] = g_idx[bn0*3 + t]; sw[t] = g_w[bn0*3 + t]; }
    __syncthreads();
    int b = bn0 >> 13;
    const float* f2t = g_f2t + (size_t)b*SPTS*D2C;
    int lx = t & 31, ly = t >> 5;
    for (int dc = 0; dc < 8; dc++) {
        int d = dc*32 + lx;
        #pragma unroll
        for (int p = ly; p < 32; p += 8) {
            float v = sw[p*3+0]*f2t[(size_t)si[p*3+0]*D2C + d]
                    + sw[p*3+1]*f2t[(size_t)si[p*3+1]*D2C + d]
                    + sw[p*3+2]*f2t[(size_t)si[p*3+2]*D2C + d];
            tile[p][lx] = v;
        }
        __syncthreads();
        #pragma unroll
        for (int dd = ly; dd < 32; dd += 8)
            g_feat[(size_t)(dc*32+dd)*BNT + bn0 + lx] = tile[lx][dd];
        __syncthreads();
    }
}

// ============================================================
// feature1 [B,D1,N] -> g_feat rows [D2, D2+D1)
// ============================================================
__global__ void copy_f1(const float* __restrict__ f1) {
    int i = blockIdx.x*blockDim.x + threadIdx.x;   // B*D1*N = 4194304
    int n   = i & (NPTS-1);
    int rem = i >> 13;
    int d   = rem & (D1C-1);
    int b   = rem >> 7;
    g_feat[(size_t)(D2C + d)*BNT + b*NPTS + n] = f1[i];
}

// ============================================================
// SGEMM 128x128 tile, 8x8 per thread, fp32.
// MODE 0: y1 = W1 @ g_feat + b1                 (K=384, out = g_y1)
// MODE 1: y2 = W2 @ relu(bn1(g_y1)) + b2       (K=256, out = d_out, [B,C,N] layout)
// ============================================================
template<int MODE>
__global__ void __launch_bounds__(256, 2)
gemm_kernel(const float* __restrict__ Wm, const float* __restrict__ bias,
            float* __restrict__ out_ext, int K) {
    __shared__ float As[8][128];
    __shared__ float Bs[8][128];

    int tid = threadIdx.x;
    int tx = tid & 15, ty = tid >> 4;
    int m0 = blockIdx.y*128, n0 = blockIdx.x*128;

    float acc[8][8];
    #pragma unroll
    for (int i = 0; i < 8; i++)
        #pragma unroll
        for (int j = 0; j < 8; j++) acc[i][j] = 0.0f;

    int a_m = tid >> 1;
    int a_k = (tid & 1)*4;
    int b_k = tid >> 5;
    int b_n = (tid & 31)*4;

    const float* Bmat = (MODE == 0) ? g_feat : g_y1;

    for (int k0 = 0; k0 < K; k0 += 8) {
        float4 av = *(const float4*)&Wm[(size_t)(m0+a_m)*K + k0 + a_k];
        As[a_k+0][a_m]=av.x; As[a_k+1][a_m]=av.y;
        As[a_k+2][a_m]=av.z; As[a_k+3][a_m]=av.w;

        float4 bv = *(const float4*)&Bmat[(size_t)(k0+b_k)*BNT + n0 + b_n];
        if (MODE == 1) {
            float sc = g_scale1[k0+b_k], sh = g_shift1[k0+b_k];
            bv.x = fmaxf(bv.x*sc+sh, 0.0f);
            bv.y = fmaxf(bv.y*sc+sh, 0.0f);
            bv.z = fmaxf(bv.z*sc+sh, 0.0f);
            bv.w = fmaxf(bv.w*sc+sh, 0.0f);
        }
        *(float4*)&Bs[b_k][b_n] = bv;
        __syncthreads();

        #pragma unroll
        for (int k = 0; k < 8; k++) {
            float ar[8], br[8];
            *(float4*)(ar)   = *(float4*)&As[k][ty*8];
            *(float4*)(ar+4) = *(float4*)&As[k][ty*8+4];
            *(float4*)(br)   = *(float4*)&Bs[k][tx*8];
            *(float4*)(br+4) = *(float4*)&Bs[k][tx*8+4];
            #pragma unroll
            for (int i = 0; i < 8; i++)
                #pragma unroll
                for (int j = 0; j < 8; j++)
                    acc[i][j] = fmaf(ar[i], br[j], acc[i][j]);
        }
        __syncthreads();
    }

    #pragma unroll
    for (int i = 0; i < 8; i++) {
        int m = m0 + ty*8 + i;
        float bb = bias[m];
        #pragma unroll
        for (int j = 0; j < 8; j++) {
            int n = n0 + tx*8 + j;
            float v = acc[i][j] + bb;
            if (MODE == 0) {
                g_y1[(size_t)m*BNT + n] = v;
            } else {
                int bidx = n >> 13, nn = n & (NPTS-1);
                out_ext[(size_t)bidx*COUT*NPTS + (size_t)m*NPTS + nn] = v;
            }
        }
    }
}

// ============================================================
// BN stats -> affine (scale, shift) per channel
// MODE 0: reads g_y1 [C, BNT], writes g_scale1/g_shift1
// MODE 1: reads d_out [B,C,N], writes g_scale2/g_shift2
// ============================================================
template<int MODE>
__global__ void bn_stats(const float* __restrict__ y_ext,
                         const float* __restrict__ g,
                         const float* __restrict__ beta) {
    int o = blockIdx.x;
    float s = 0.0f, s2 = 0.0f;
    for (int e = threadIdx.x; e < BNT; e += blockDim.x) {
        float v;
        if (MODE == 0) v = g_y1[(size_t)o*BNT + e];
        else {
            int b = e >> 13, n = e & (NPTS-1);
            v = y_ext[(size_t)b*COUT*NPTS + (size_t)o*NPTS + n];
        }
        s += v; s2 += v*v;
    }
    __shared__ float rs[256], rs2[256];
    rs[threadIdx.x] = s; rs2[threadIdx.x] = s2;
    __syncthreads();
    for (int off = 128; off > 0; off >>= 1) {
        if (threadIdx.x < off) {
            rs[threadIdx.x]  += rs[threadIdx.x+off];
            rs2[threadIdx.x] += rs2[threadIdx.x+off];
        }
        __syncthreads();
    }
    if (threadIdx.x == 0) {
        float mean = rs[0] * (1.0f/(float)BNT);
        float var  = rs2[0]*(1.0f/(float)BNT) - mean*mean;
        float r  = rsqrtf(var + 1e-5f);
        float sc = g[o]*r;
        float sh = beta[o] - mean*sc;
        if (MODE == 0) { g_scale1[o]=sc; g_shift1[o]=sh; }
        else           { g_scale2[o]=sc; g_shift2[o]=sh; }
    }
}

// ============================================================
// final in-place BN+ReLU on d_out
// ============================================================
__global__ void bn_relu_final(float* __restrict__ out) {
    int i = blockIdx.x*blockDim.x + threadIdx.x;   // 8388608
    int o = (i >> 13) & (COUT-1);
    float v = out[i]*g_scale2[o] + g_shift2[o];
    out[i] = fmaxf(v, 0.0f);
}

// ============================================================
extern "C" void kernel_launch(void* const* d_in, const int* in_sizes, int n_in,
                              void* d_out, int out_size) {
    const float* pos1 = (const float*)d_in[0];
    const float* pos2 = (const float*)d_in[1];
    const float* f1   = (const float*)d_in[2];
    const float* f2   = (const float*)d_in[3];
    const float* W1   = (const float*)d_in[4];
    const float* b1   = (const float*)d_in[5];
    const float* g1   = (const float*)d_in[6];
    const float* be1  = (const float*)d_in[7];
    const float* W2   = (const float*)d_in[8];
    const float* b2   = (const float*)d_in[9];
    const float* g2   = (const float*)d_in[10];
    const float* be2  = (const float*)d_in[11];
    float* out = (float*)d_out;

    knn_kernel   <<<dim3(NPTS/256, BB), 256>>>(pos1, pos2);
    transpose_f2 <<<dim3(SPTS/32, D2C/32, BB), dim3(32,8)>>>(f2);
    interp_kernel<<<BNT/32, 256>>>();
    copy_f1      <<<(BB*D1C*NPTS)/256, 256>>>(f1);

    gemm_kernel<0><<<dim3(BNT/128, CMID/128), 256>>>(W1, b1, nullptr, CIN);
    bn_stats<0>   <<<CMID, 256>>>(nullptr, g1, be1);
    gemm_kernel<1><<<dim3(BNT/128, COUT/128), 256>>>(W2, b2, out, CMID);
    bn_stats<1>   <<<COUT, 256>>>(out, g2, be2);
    bn_relu_final <<<(BB*COUT*NPTS)/256, 256>>>(out);
}

// round 9
// speedup vs baseline: 1.7700x; 1.7700x over previous
#include <cuda_runtime.h>
#include <cuda_bf16.h>
#include <math.h>
#include <stdint.h>

#define BB    4
#define NPTS  8192
#define SPTS  2048
#define D1C   128
#define D2C   256
#define CIN   384
#define CMID  256
#define COUT  256
#define BNT   (BB*NPTS)     // 32768
#define KP1   (3*CIN)       // 1152
#define KP2   (3*CMID)      // 768
#define KCH1  (KP1/64)      // 18 chunks of 64
#define KCH2  (KP2/64)      // 12

// ---------------- scratch (device globals) ----------------
__device__ __align__(256) float          g_f2t[BB*SPTS*D2C];          // [B,S,D2]
__device__ __align__(256) __nv_bfloat16  g_featB[(size_t)BNT*KP1];    // B op GEMM1, point-major
__device__ __align__(256) __nv_bfloat16  g_W1e[CMID*KP1];             // A op GEMM1
__device__ __align__(256) __nv_bfloat16  g_W2e[COUT*KP2];             // A op GEMM2
__device__ __align__(256) float          g_y1T[(size_t)BNT*CMID];     // y1 pre-BN, point-major
__device__ __align__(256) __nv_bfloat16  g_y2B[(size_t)BNT*KP2];      // B op GEMM2
__device__ __align__(256) float          g_y2T[(size_t)BNT*COUT];     // y2 pre-BN, point-major
__device__ int   g_idx[BNT*3];
__device__ float g_w[BNT*3];
__device__ float g_sum1[CMID], g_sq1[CMID], g_sum2[COUT], g_sq2[COUT];
__device__ float g_sc1[CMID], g_sh1[CMID], g_sc2[COUT], g_sh2[COUT];

// ---------------- small helpers ----------------
__device__ __forceinline__ void cp16(uint32_t dst, const void* src){
    asm volatile("cp.async.cg.shared.global [%0], [%1], 16;" :: "r"(dst), "l"(src));
}
__device__ __forceinline__ void ldm4(uint32_t* r, uint32_t addr){
    asm volatile("ldmatrix.sync.aligned.m8n8.x4.shared.b16 {%0,%1,%2,%3}, [%4];"
        : "=r"(r[0]), "=r"(r[1]), "=r"(r[2]), "=r"(r[3]) : "r"(addr));
}
__device__ __forceinline__ void mma16816(float* d, const uint32_t* a, uint32_t b0, uint32_t b1){
    asm volatile(
        "mma.sync.aligned.m16n8k16.row.col.f32.bf16.bf16.f32 "
        "{%0,%1,%2,%3}, {%4,%5,%6,%7}, {%8,%9}, {%0,%1,%2,%3};"
        : "+f"(d[0]), "+f"(d[1]), "+f"(d[2]), "+f"(d[3])
        : "r"(a[0]), "r"(a[1]), "r"(a[2]), "r"(a[3]), "r"(b0), "r"(b1));
}

__device__ __forceinline__ void split_bf(float v, uint32_t& hi, uint32_t& lo){
    __nv_bfloat16 h = __float2bfloat16(v);
    float r = v - __bfloat162float(h);
    __nv_bfloat16 l = __float2bfloat16(r);
    hi = (uint32_t)__bfloat16_as_ushort(h);
    lo = (uint32_t)__bfloat16_as_ushort(l);
}

// B-side pattern per channel: [hi, lo, hi]; packs 4 channels -> 6 uint32
__device__ __forceinline__ void packB4(const float* v, uint32_t* u){
    uint32_t h[4], l[4];
    #pragma unroll
    for (int j = 0; j < 4; j++) split_bf(v[j], h[j], l[j]);
    u[0] = h[0] | (l[0] << 16);
    u[1] = h[0] | (h[1] << 16);
    u[2] = l[1] | (h[1] << 16);
    u[3] = h[2] | (l[2] << 16);
    u[4] = h[2] | (h[3] << 16);
    u[5] = l[3] | (h[3] << 16);
}

// ============================================================
__global__ void zero_acc(){
    int t = threadIdx.x;
    g_sum1[t] = 0.f; g_sq1[t] = 0.f; g_sum2[t] = 0.f; g_sq2[t] = 0.f;
}

// ============================================================
// 3-NN
// ============================================================
__global__ void knn_kernel(const float* __restrict__ pos1,
                           const float* __restrict__ pos2) {
    __shared__ float sx[SPTS], sy[SPTS], sz[SPTS], sn[SPTS];
    int b = blockIdx.y;
    const float* p2 = pos2 + (size_t)b*3*SPTS;
    for (int s = threadIdx.x; s < SPTS; s += blockDim.x) {
        float x = p2[s], y = p2[SPTS+s], z = p2[2*SPTS+s];
        sx[s]=x; sy[s]=y; sz[s]=z; sn[s]=x*x+y*y+z*z;
    }
    __syncthreads();

    int n = blockIdx.x*blockDim.x + threadIdx.x;
    const float* p1 = pos1 + (size_t)b*3*NPTS;
    float px = p1[n], py = p1[NPTS+n], pz = p1[2*NPTS+n];
    float n1 = px*px+py*py+pz*pz;

    float d0v=1e30f, d1v=1e30f, d2v=1e30f;
    int   i0=0, i1=0, i2=0;
    #pragma unroll 4
    for (int s = 0; s < SPTS; s++) {
        float dot = px*sx[s] + py*sy[s] + pz*sz[s];
        float d = n1 - 2.0f*dot + sn[s];
        if (d < d2v) {
            if (d < d1v) {
                d2v = d1v; i2 = i1;
                if (d < d0v) { d1v = d0v; i1 = i0; d0v = d; i0 = s; }
                else         { d1v = d;   i1 = s; }
            } else { d2v = d; i2 = s; }
        }
    }
    float a0 = fmaxf(d0v, 1e-10f), a1 = fmaxf(d1v, 1e-10f), a2 = fmaxf(d2v, 1e-10f);
    float w0 = 1.0f/a0, w1 = 1.0f/a1, w2 = 1.0f/a2;
    float inv = 1.0f/(w0+w1+w2);
    int base = (b*NPTS + n)*3;
    g_idx[base+0]=i0; g_idx[base+1]=i1; g_idx[base+2]=i2;
    g_w[base+0]=w0*inv; g_w[base+1]=w1*inv; g_w[base+2]=w2*inv;
}

// ============================================================
// feature2 [B,D2,S] -> g_f2t [B,S,D2]
// ============================================================
__global__ void transpose_f2(const float* __restrict__ f2) {
    __shared__ float t[32][33];
    int b = blockIdx.z;
    int d0 = blockIdx.y*32, s0 = blockIdx.x*32;
    int lx = threadIdx.x, ly = threadIdx.y;
    const float* src = f2 + (size_t)b*D2C*SPTS;
    #pragma unroll
    for (int i = ly; i < 32; i += 8)
        t[i][lx] = src[(size_t)(d0+i)*SPTS + s0 + lx];
    __syncthreads();
    float* dst = g_f2t + (size_t)b*SPTS*D2C;
    #pragma unroll
    for (int i = ly; i < 32; i += 8)
        dst[(size_t)(s0+i)*D2C + d0 + lx] = t[lx][i];
}

// ============================================================
// interp: weighted 3-NN -> g_featB rows k'=[0, 3*D2)
// ============================================================
__global__ void interp_kernel() {
    int t = threadIdx.x;
    int p = blockIdx.x*4 + (t >> 6);
    int kg = t & 63;
    int i0 = __ldg(&g_idx[p*3+0]), i1 = __ldg(&g_idx[p*3+1]), i2 = __ldg(&g_idx[p*3+2]);
    float w0 = __ldg(&g_w[p*3+0]), w1 = __ldg(&g_w[p*3+1]), w2 = __ldg(&g_w[p*3+2]);
    int b = p >> 13;
    const float* f2 = g_f2t + (size_t)b*SPTS*D2C;
    int k0 = kg*4;
    float4 a = *(const float4*)&f2[(size_t)i0*D2C + k0];
    float4 c = *(const float4*)&f2[(size_t)i1*D2C + k0];
    float4 d = *(const float4*)&f2[(size_t)i2*D2C + k0];
    float v[4];
    v[0] = w0*a.x + w1*c.x + w2*d.x;
    v[1] = w0*a.y + w1*c.y + w2*d.y;
    v[2] = w0*a.z + w1*c.z + w2*d.z;
    v[3] = w0*a.w + w1*c.w + w2*d.w;
    uint32_t u[6]; packB4(v, u);
    uint32_t* dst = (uint32_t*)((char*)g_featB + (size_t)p*KP1*2 + (size_t)k0*6);
    #pragma unroll
    for (int j = 0; j < 6; j++) dst[j] = u[j];
}

// ============================================================
// feature1 [B,D1,N] -> g_featB rows k'=[3*D2, 3*CIN)
// ============================================================
__global__ void copy_f1(const float* __restrict__ f1) {
    __shared__ float tile[32][33];
    int b = blockIdx.z, d0 = blockIdx.y*32, n0 = blockIdx.x*32;
    int lx = threadIdx.x, ly = threadIdx.y;
    const float* src = f1 + ((size_t)b*D1C + d0)*NPTS + n0;
    #pragma unroll
    for (int i = ly; i < 32; i += 8)
        tile[i][lx] = src[(size_t)i*NPTS + lx];
    __syncthreads();
    int t = ly*32 + lx;
    int g = t & 7, nn = t >> 3;
    int n = b*NPTS + n0 + nn;
    int d = d0 + g*4;
    float v[4];
    #pragma unroll
    for (int j = 0; j < 4; j++) v[j] = tile[g*4+j][nn];
    uint32_t u[6]; packB4(v, u);
    uint32_t* dst = (uint32_t*)((char*)g_featB + (size_t)n*KP1*2 + (size_t)(D2C + d)*6);
    #pragma unroll
    for (int j = 0; j < 6; j++) dst[j] = u[j];
}

// ============================================================
// weight expand: A-side pattern per channel: [hi, hi, lo]
// ============================================================
template<int MODE>
__global__ void wexpand(const float* __restrict__ W) {
    constexpr int K = (MODE == 0) ? CIN : CMID;
    __nv_bfloat16* We = (MODE == 0) ? g_W1e : g_W2e;
    int i = blockIdx.x*blockDim.x + threadIdx.x;   // 256*K
    int m = i / K, k = i - m*K;
    float v = W[i];
    uint32_t hi, lo; split_bf(v, hi, lo);
    __nv_bfloat16* p = We + (size_t)m*3*K + 3*k;
    p[0] = __ushort_as_bfloat16((unsigned short)hi);
    p[1] = __ushort_as_bfloat16((unsigned short)hi);
    p[2] = __ushort_as_bfloat16((unsigned short)lo);
}

// ============================================================
// mma.sync GEMM: CTA tile 128(m) x 128(n) x 64(k'), 8 warps (2m x 4n),
// warp tile 64x32 via m16n8k16 bf16. Double-buffered cp.async.
// Epilogue: bias, stage through smem, coalesced store point-major,
// per-channel BN sum/sumsq atomics.
// ============================================================
#define SMEM_DYN 67072

template<int Kp>
__device__ __forceinline__ void load_chunk(uint32_t sA, uint32_t sB,
        const __nv_bfloat16* __restrict__ A, const __nv_bfloat16* __restrict__ B,
        int m0, int n0, int c, int t) {
    int seg = t & 7, r0 = t >> 3;
    const char* Ab = (const char*)A + ((size_t)m0*Kp + c*64)*2 + (size_t)seg*16;
    const char* Bb = (const char*)B + ((size_t)n0*Kp + c*64)*2 + (size_t)seg*16;
    #pragma unroll
    for (int i = 0; i < 4; i++) {
        int row = r0 + i*32;
        uint32_t sw = (uint32_t)(seg ^ (row & 7))*16u;
        cp16(sA + row*128 + sw, Ab + (size_t)row*Kp*2);
        cp16(sB + row*128 + sw, Bb + (size_t)row*Kp*2);
    }
    asm volatile("cp.async.commit_group;" ::: "memory");
}

template<int MODE>
__global__ void __launch_bounds__(256)
mma_gemm(const float* __restrict__ bias) {
    constexpr int KCH = (MODE == 0) ? KCH1 : KCH2;
    constexpr int Kp  = KCH*64;
    const __nv_bfloat16* A = (MODE == 0) ? g_W1e  : g_W2e;
    const __nv_bfloat16* B = (MODE == 0) ? g_featB : g_y2B;
    float* yT   = (MODE == 0) ? g_y1T : g_y2T;
    float* sacc = (MODE == 0) ? g_sum1 : g_sum2;
    float* qacc = (MODE == 0) ? g_sq1  : g_sq2;

    extern __shared__ char smem[];
    uint32_t sb;
    asm("{ .reg .u64 t; cvta.to.shared.u64 t, %1; cvt.u32.u64 %0, t; }"
        : "=r"(sb) : "l"(smem));
    uint32_t base = (sb + 127u) & ~127u;
    uint32_t sA0 = base, sA1 = base + 16384;
    uint32_t sB0 = base + 32768, sB1 = base + 49152;
    float* stage = (float*)(size_t)0; // set via pointer arithmetic below
    stage = (float*)(smem + (base - sb) + 0);   // same region as operands (reused)

    int t = threadIdx.x, wid = t >> 5, lane = t & 31;
    int wm = wid & 1, wn = wid >> 1;
    int m0 = blockIdx.y*128, n0 = blockIdx.x*128;
    int m0w = wm*64, n0w = wn*32;

    float acc[4][4][4];
    #pragma unroll
    for (int i = 0; i < 4; i++)
        #pragma unroll
        for (int j = 0; j < 4; j++)
            #pragma unroll
            for (int e = 0; e < 4; e++) acc[i][j][e] = 0.f;

    int laneRow = lane & 15, laneHi = lane >> 4;

    load_chunk<Kp>(sA0, sB0, A, B, m0, n0, 0, t);

    for (int c = 0; c < KCH; c++) {
        if (c + 1 < KCH)
            load_chunk<Kp>((c & 1) ? sA0 : sA1, (c & 1) ? sB0 : sB1,
                           A, B, m0, n0, c + 1, t);
        if (c + 1 < KCH) asm volatile("cp.async.wait_group 1;" ::: "memory");
        else             asm volatile("cp.async.wait_group 0;" ::: "memory");
        __syncthreads();
        uint32_t curA = (c & 1) ? sA1 : sA0;
        uint32_t curB = (c & 1) ? sB1 : sB0;

        #pragma unroll
        for (int ks = 0; ks < 4; ks++) {
            int seg = 2*ks + laneHi;
            uint32_t a[4][4], b[2][4];
            #pragma unroll
            for (int mi = 0; mi < 4; mi++) {
                int row = m0w + 16*mi + laneRow;
                ldm4(a[mi], curA + row*128 + (uint32_t)(seg ^ (row & 7))*16u);
            }
            #pragma unroll
            for (int nj = 0; nj < 2; nj++) {
                int row = n0w + 16*nj + laneRow;
                ldm4(b[nj], curB + row*128 + (uint32_t)(seg ^ (row & 7))*16u);
            }
            #pragma unroll
            for (int mi = 0; mi < 4; mi++)
                #pragma unroll
                for (int f = 0; f < 4; f++)
                    mma16816(acc[mi][f], a[mi], b[f>>1][f&1], b[f>>1][(f&1)+2]);
        }
        __syncthreads();
    }

    // ---- epilogue: stage [n(128)][m(128)] fp32 with pad 130 ----
    {
        int q = lane & 3, r = lane >> 2;
        #pragma unroll
        for (int mi = 0; mi < 4; mi++) {
            int m_l = wm*64 + 16*mi + r;
            #pragma unroll
            for (int f = 0; f < 4; f++) {
                int n_l = wn*32 + 8*f + 2*q;
                stage[(size_t)n_l*130 + m_l]          = acc[mi][f][0];
                stage[(size_t)(n_l+1)*130 + m_l]      = acc[mi][f][1];
                stage[(size_t)n_l*130 + m_l + 8]      = acc[mi][f][2];
                stage[(size_t)(n_l+1)*130 + m_l + 8]  = acc[mi][f][3];
            }
        }
    }
    __syncthreads();

    // coalesced store: yT[(n0+n)*256 + m0 + m], bias added
    for (int idx = t; idx < 128*32; idx += 256) {
        int n_l = idx >> 5, m4 = idx & 31;
        float4 bb = __ldg((const float4*)&bias[m0 + m4*4]);
        float* sp = &stage[(size_t)n_l*130 + m4*4];
        float4 v;
        v.x = sp[0] + bb.x; v.y = sp[1] + bb.y;
        v.z = sp[2] + bb.z; v.w = sp[3] + bb.w;
        *(float4*)&yT[(size_t)(n0 + n_l)*256 + m0 + m4*4] = v;
    }

    // BN sums: thread t -> channel m_l = t&127, half nh = t>>7
    {
        int m_l = t & 127, nh = t >> 7;
        float bb = __ldg(&bias[m0 + m_l]);
        float s = 0.f, q = 0.f;
        #pragma unroll 4
        for (int j = 0; j < 64; j++) {
            float v = stage[(size_t)(nh*64 + j)*130 + m_l] + bb;
            s += v; q += v*v;
        }
        atomicAdd(&sacc[m0 + m_l], s);
        atomicAdd(&qacc[m0 + m_l], q);
    }
}

// ============================================================
// BN finalize
// ============================================================
template<int MODE>
__global__ void bn_fin(const float* __restrict__ g, const float* __restrict__ beta) {
    int o = threadIdx.x;
    float s  = (MODE == 0) ? g_sum1[o] : g_sum2[o];
    float s2 = (MODE == 0) ? g_sq1[o]  : g_sq2[o];
    float mean = s * (1.0f/(float)BNT);
    float var  = s2 * (1.0f/(float)BNT) - mean*mean;
    float r = rsqrtf(var + 1e-5f);
    float sc = g[o]*r;
    float sh = beta[o] - mean*sc;
    if (MODE == 0) { g_sc1[o] = sc; g_sh1[o] = sh; }
    else           { g_sc2[o] = sc; g_sh2[o] = sh; }
}

// ============================================================
// prep2: relu(bn1(y1)) -> bf16 split-expanded B operand for GEMM2
// ============================================================
__global__ void prep2() {
    int i = blockIdx.x*blockDim.x + threadIdx.x;   // BNT*64
    int n = i >> 6, kg = i & 63, k0 = kg*4;
    float4 y = *(const float4*)&g_y1T[(size_t)n*CMID + k0];
    float v[4];
    v[0] = fmaxf(y.x*g_sc1[k0+0] + g_sh1[k0+0], 0.f);
    v[1] = fmaxf(y.y*g_sc1[k0+1] + g_sh1[k0+1], 0.f);
    v[2] = fmaxf(y.z*g_sc1[k0+2] + g_sh1[k0+2], 0.f);
    v[3] = fmaxf(y.w*g_sc1[k0+3] + g_sh1[k0+3], 0.f);
    uint32_t u[6]; packB4(v, u);
    uint32_t* dst = (uint32_t*)((char*)g_y2B + (size_t)n*KP2*2 + (size_t)k0*6);
    #pragma unroll
    for (int j = 0; j < 6; j++) dst[j] = u[j];
}

// ============================================================
// final: y2T [n][m] -> out [b][m][n] with BN2+ReLU
// ============================================================
__global__ void final_out(float* __restrict__ out) {
    __shared__ float tile[32][33];
    int b = blockIdx.z, m0 = blockIdx.y*32, n0 = blockIdx.x*32;
    int lx = threadIdx.x, ly = threadIdx.y;
    #pragma unroll
    for (int i = ly; i < 32; i += 8)
        tile[i][lx] = g_y2T[(size_t)(b*NPTS + n0 + i)*COUT + m0 + lx];
    __syncthreads();
    #pragma unroll
    for (int i = ly; i < 32; i += 8) {
        int m = m0 + i;
        float v = tile[lx][i]*g_sc2[m] + g_sh2[m];
        out[((size_t)b*COUT + m)*NPTS + n0 + lx] = fmaxf(v, 0.f);
    }
}

// ============================================================
extern "C" void kernel_launch(void* const* d_in, const int* in_sizes, int n_in,
                              void* d_out, int out_size) {
    const float* pos1 = (const float*)d_in[0];
    const float* pos2 = (const float*)d_in[1];
    const float* f1   = (const float*)d_in[2];
    const float* f2   = (const float*)d_in[3];
    const float* W1   = (const float*)d_in[4];
    const float* b1   = (const float*)d_in[5];
    const float* g1   = (const float*)d_in[6];
    const float* be1  = (const float*)d_in[7];
    const float* W2   = (const float*)d_in[8];
    const float* b2   = (const float*)d_in[9];
    const float* g2   = (const float*)d_in[10];
    const float* be2  = (const float*)d_in[11];
    float* out = (float*)d_out;

    cudaFuncSetAttribute(mma_gemm<0>, cudaFuncAttributeMaxDynamicSharedMemorySize, SMEM_DYN);
    cudaFuncSetAttribute(mma_gemm<1>, cudaFuncAttributeMaxDynamicSharedMemorySize, SMEM_DYN);

    zero_acc     <<<1, 256>>>();
    knn_kernel   <<<dim3(NPTS/256, BB), 256>>>(pos1, pos2);
    transpose_f2 <<<dim3(SPTS/32, D2C/32, BB), dim3(32,8)>>>(f2);
    interp_kernel<<<BNT/4, 256>>>();
    copy_f1      <<<dim3(NPTS/32, D1C/32, BB), dim3(32,8)>>>(f1);
    wexpand<0>   <<<(CMID*CIN)/256, 256>>>(W1);
    wexpand<1>   <<<(COUT*CMID)/256, 256>>>(W2);

    mma_gemm<0>  <<<dim3(BNT/128, 2), 256, SMEM_DYN>>>(b1);
    bn_fin<0>    <<<1, 256>>>(g1, be1);
    prep2        <<<(BNT*64)/256, 256>>>();
    mma_gemm<1>  <<<dim3(BNT/128, 2), 256, SMEM_DYN>>>(b2);
    bn_fin<1>    <<<1, 256>>>(g2, be2);
    final_out    <<<dim3(NPTS/32, COUT/32, BB), dim3(32,8)>>>(out);
}

// round 10
// speedup vs baseline: 1.8506x; 1.0456x over previous
#include <cuda_runtime.h>
#include <cuda_bf16.h>
#include <math.h>
#include <stdint.h>

#define BB    4
#define NPTS  8192
#define SPTS  2048
#define D1C   128
#define D2C   256
#define CIN   384
#define CMID  256
#define COUT  256
#define BNT   (BB*NPTS)     // 32768
#define KP1   (3*CIN)       // 1152
#define KP2   (3*CMID)      // 768
#define KCH1  (KP1/64)      // 18 chunks of 64
#define KCH2  (KP2/64)      // 12

// ---------------- scratch (device globals) ----------------
__device__ __align__(256) float          g_f2t[BB*SPTS*D2C];          // [B,S,D2]
__device__ __align__(256) __nv_bfloat16  g_featB[(size_t)BNT*KP1];    // B op GEMM1, point-major
__device__ __align__(256) __nv_bfloat16  g_W1e[CMID*KP1];             // A op GEMM1
__device__ __align__(256) __nv_bfloat16  g_W2e[COUT*KP2];             // A op GEMM2
__device__ __align__(256) float          g_y1T[(size_t)BNT*CMID];     // y1 pre-BN, point-major
__device__ __align__(256) __nv_bfloat16  g_y2B[(size_t)BNT*KP2];      // B op GEMM2
__device__ __align__(256) float          g_y2T[(size_t)BNT*COUT];     // y2 pre-BN, point-major
__device__ int   g_idx[BNT*3];
__device__ float g_w[BNT*3];
__device__ float g_sum1[CMID], g_sq1[CMID], g_sum2[COUT], g_sq2[COUT];

// ---------------- small helpers ----------------
__device__ __forceinline__ void cp16(uint32_t dst, const void* src){
    asm volatile("cp.async.cg.shared.global [%0], [%1], 16;" :: "r"(dst), "l"(src));
}
__device__ __forceinline__ void ldm4(uint32_t* r, uint32_t addr){
    asm volatile("ldmatrix.sync.aligned.m8n8.x4.shared.b16 {%0,%1,%2,%3}, [%4];"
        : "=r"(r[0]), "=r"(r[1]), "=r"(r[2]), "=r"(r[3]) : "r"(addr));
}
__device__ __forceinline__ void mma16816(float* d, const uint32_t* a, uint32_t b0, uint32_t b1){
    asm volatile(
        "mma.sync.aligned.m16n8k16.row.col.f32.bf16.bf16.f32 "
        "{%0,%1,%2,%3}, {%4,%5,%6,%7}, {%8,%9}, {%0,%1,%2,%3};"
        : "+f"(d[0]), "+f"(d[1]), "+f"(d[2]), "+f"(d[3])
        : "r"(a[0]), "r"(a[1]), "r"(a[2]), "r"(a[3]), "r"(b0), "r"(b1));
}

__device__ __forceinline__ void split_bf(float v, uint32_t& hi, uint32_t& lo){
    __nv_bfloat16 h = __float2bfloat16(v);
    float r = v - __bfloat162float(h);
    __nv_bfloat16 l = __float2bfloat16(r);
    hi = (uint32_t)__bfloat16_as_ushort(h);
    lo = (uint32_t)__bfloat16_as_ushort(l);
}

// B-side pattern per channel: [hi, lo, hi]; packs 4 channels -> 6 uint32
__device__ __forceinline__ void packB4(const float* v, uint32_t* u){
    uint32_t h[4], l[4];
    #pragma unroll
    for (int j = 0; j < 4; j++) split_bf(v[j], h[j], l[j]);
    u[0] = h[0] | (l[0] << 16);
    u[1] = h[0] | (h[1] << 16);
    u[2] = l[1] | (h[1] << 16);
    u[3] = h[2] | (l[2] << 16);
    u[4] = h[2] | (h[3] << 16);
    u[5] = l[3] | (h[3] << 16);
}

// 8 channels -> 3 x uint4 (48 bytes, 16B-aligned when k0 % 8 == 0)
__device__ __forceinline__ void store_pack8(void* dst, const float* v){
    uint32_t u[12];
    packB4(v, u); packB4(v + 4, u + 6);
    uint4* d4 = (uint4*)dst;
    d4[0] = make_uint4(u[0], u[1], u[2],  u[3]);
    d4[1] = make_uint4(u[4], u[5], u[6],  u[7]);
    d4[2] = make_uint4(u[8], u[9], u[10], u[11]);
}

// ============================================================
// 3-NN (block (0,0) also zeroes BN accumulators)
// ============================================================
__global__ void knn_kernel(const float* __restrict__ pos1,
                           const float* __restrict__ pos2) {
    __shared__ float4 sp[SPTS];
    int b = blockIdx.y;
    if (blockIdx.x == 0 && blockIdx.y == 0) {
        int t = threadIdx.x;
        g_sum1[t] = 0.f; g_sq1[t] = 0.f; g_sum2[t] = 0.f; g_sq2[t] = 0.f;
    }
    const float* p2 = pos2 + (size_t)b*3*SPTS;
    for (int s = threadIdx.x; s < SPTS; s += blockDim.x) {
        float x = p2[s], y = p2[SPTS+s], z = p2[2*SPTS+s];
        sp[s] = make_float4(x, y, z, x*x+y*y+z*z);
    }
    __syncthreads();

    int n = blockIdx.x*blockDim.x + threadIdx.x;
    const float* p1 = pos1 + (size_t)b*3*NPTS;
    float px = p1[n], py = p1[NPTS+n], pz = p1[2*NPTS+n];
    float n1 = px*px+py*py+pz*pz;

    float d0v=1e30f, d1v=1e30f, d2v=1e30f;
    int   i0=0, i1=0, i2=0;
    #pragma unroll 4
    for (int s = 0; s < SPTS; s++) {
        float4 c = sp[s];
        float d = n1 - 2.0f*(px*c.x + py*c.y + pz*c.z) + c.w;
        if (d < d2v) {
            if (d < d1v) {
                d2v = d1v; i2 = i1;
                if (d < d0v) { d1v = d0v; i1 = i0; d0v = d; i0 = s; }
                else         { d1v = d;   i1 = s; }
            } else { d2v = d; i2 = s; }
        }
    }
    float a0 = fmaxf(d0v, 1e-10f), a1 = fmaxf(d1v, 1e-10f), a2 = fmaxf(d2v, 1e-10f);
    float w0 = 1.0f/a0, w1 = 1.0f/a1, w2 = 1.0f/a2;
    float inv = 1.0f/(w0+w1+w2);
    int base = (b*NPTS + n)*3;
    g_idx[base+0]=i0; g_idx[base+1]=i1; g_idx[base+2]=i2;
    g_w[base+0]=w0*inv; g_w[base+1]=w1*inv; g_w[base+2]=w2*inv;
}

// ============================================================
// feature2 [B,D2,S] -> g_f2t [B,S,D2]
// ============================================================
__global__ void transpose_f2(const float* __restrict__ f2) {
    __shared__ float t[32][33];
    int b = blockIdx.z;
    int d0 = blockIdx.y*32, s0 = blockIdx.x*32;
    int lx = threadIdx.x, ly = threadIdx.y;
    const float* src = f2 + (size_t)b*D2C*SPTS;
    #pragma unroll
    for (int i = ly; i < 32; i += 8)
        t[i][lx] = src[(size_t)(d0+i)*SPTS + s0 + lx];
    __syncthreads();
    float* dst = g_f2t + (size_t)b*SPTS*D2C;
    #pragma unroll
    for (int i = ly; i < 32; i += 8)
        dst[(size_t)(s0+i)*D2C + d0 + lx] = t[lx][i];
}

// ============================================================
// interp: weighted 3-NN -> g_featB rows k'=[0, 3*D2)
// block = 8 points x 32 threads (8 channels/thread, uint4 stores)
// ============================================================
__global__ void interp_kernel() {
    int t = threadIdx.x;
    int p = blockIdx.x*8 + (t >> 5);
    int kg = t & 31;
    int i0 = __ldg(&g_idx[p*3+0]), i1 = __ldg(&g_idx[p*3+1]), i2 = __ldg(&g_idx[p*3+2]);
    float w0 = __ldg(&g_w[p*3+0]), w1 = __ldg(&g_w[p*3+1]), w2 = __ldg(&g_w[p*3+2]);
    int b = p >> 13;
    const float* f2 = g_f2t + (size_t)b*SPTS*D2C;
    int k0 = kg*8;
    float v[8];
    #pragma unroll
    for (int h = 0; h < 2; h++) {
        float4 a = *(const float4*)&f2[(size_t)i0*D2C + k0 + h*4];
        float4 c = *(const float4*)&f2[(size_t)i1*D2C + k0 + h*4];
        float4 d = *(const float4*)&f2[(size_t)i2*D2C + k0 + h*4];
        v[h*4+0] = w0*a.x + w1*c.x + w2*d.x;
        v[h*4+1] = w0*a.y + w1*c.y + w2*d.y;
        v[h*4+2] = w0*a.z + w1*c.z + w2*d.z;
        v[h*4+3] = w0*a.w + w1*c.w + w2*d.w;
    }
    store_pack8((char*)g_featB + (size_t)p*KP1*2 + (size_t)k0*6, v);
}

// ============================================================
// feature1 [B,D1,N] -> g_featB rows k'=[3*D2, 3*CIN)
// tile 64(d) x 32(n); 8 channels/thread, uint4 stores
// ============================================================
__global__ void copy_f1(const float* __restrict__ f1) {
    __shared__ float tile[64][33];
    int b = blockIdx.z, d0 = blockIdx.y*64, n0 = blockIdx.x*32;
    int t = threadIdx.x;
    int lx = t & 31, ly = t >> 5;
    const float* src = f1 + ((size_t)b*D1C + d0)*NPTS + n0;
    #pragma unroll
    for (int i = ly; i < 64; i += 8)
        tile[i][lx] = src[(size_t)i*NPTS + lx];
    __syncthreads();
    int g = t & 7, nn = t >> 3;
    int n = b*NPTS + n0 + nn;
    int d = d0 + g*8;
    float v[8];
    #pragma unroll
    for (int j = 0; j < 8; j++) v[j] = tile[g*8+j][nn];
    store_pack8((char*)g_featB + (size_t)n*KP1*2 + (size_t)(D2C + d)*6, v);
}

// ============================================================
// weight expand (both layers in one launch): A pattern [hi, hi, lo]
// ============================================================
__global__ void wexpand_all(const float* __restrict__ W1,
                            const float* __restrict__ W2) {
    int i = blockIdx.x*blockDim.x + threadIdx.x;   // CMID*CIN + COUT*CMID
    float v; __nv_bfloat16* p;
    if (i < CMID*CIN) {
        int m = i / CIN, k = i - m*CIN;
        v = W1[i];
        p = g_W1e + (size_t)m*KP1 + 3*k;
    } else {
        int j = i - CMID*CIN;
        int m = j / CMID, k = j - m*CMID;
        v = W2[j];
        p = g_W2e + (size_t)m*KP2 + 3*k;
    }
    uint32_t hi, lo; split_bf(v, hi, lo);
    p[0] = __ushort_as_bfloat16((unsigned short)hi);
    p[1] = __ushort_as_bfloat16((unsigned short)hi);
    p[2] = __ushort_as_bfloat16((unsigned short)lo);
}

// ============================================================
// mma.sync GEMM: CTA 128m x 128n x 64k, 8 warps (2m x 4n), warp 64x32.
// 3-stage cp.async pipeline (prefetch distance 2).
// Epilogue: bias, smem stage, coalesced point-major store, BN atomics.
// ============================================================
#define SMEM_DYN 98432

template<int Kp>
__device__ __forceinline__ void load_chunk(uint32_t sA, uint32_t sB,
        const __nv_bfloat16* __restrict__ A, const __nv_bfloat16* __restrict__ B,
        int m0, int n0, int c, int t) {
    int seg = t & 7, r0 = t >> 3;
    const char* Ab = (const char*)A + ((size_t)m0*Kp + c*64)*2 + (size_t)seg*16;
    const char* Bb = (const char*)B + ((size_t)n0*Kp + c*64)*2 + (size_t)seg*16;
    #pragma unroll
    for (int i = 0; i < 4; i++) {
        int row = r0 + i*32;
        uint32_t sw = (uint32_t)(seg ^ (row & 7))*16u;
        cp16(sA + row*128 + sw, Ab + (size_t)row*Kp*2);
        cp16(sB + row*128 + sw, Bb + (size_t)row*Kp*2);
    }
    asm volatile("cp.async.commit_group;" ::: "memory");
}

template<int MODE>
__global__ void __launch_bounds__(256)
mma_gemm(const float* __restrict__ bias) {
    constexpr int KCH = (MODE == 0) ? KCH1 : KCH2;
    constexpr int Kp  = KCH*64;
    const __nv_bfloat16* A = (MODE == 0) ? g_W1e  : g_W2e;
    const __nv_bfloat16* B = (MODE == 0) ? g_featB : g_y2B;
    float* yT   = (MODE == 0) ? g_y1T : g_y2T;
    float* sacc = (MODE == 0) ? g_sum1 : g_sum2;
    float* qacc = (MODE == 0) ? g_sq1  : g_sq2;

    extern __shared__ char smem[];
    uint32_t sb;
    asm("{ .reg .u64 t; cvta.to.shared.u64 t, %1; cvt.u32.u64 %0, t; }"
        : "=r"(sb) : "l"(smem));
    uint32_t base = (sb + 127u) & ~127u;
    uint32_t sAb[3] = { base,         base + 16384u, base + 32768u };
    uint32_t sBb[3] = { base + 49152u, base + 65536u, base + 81920u };
    float* stage = (float*)(smem + (base - sb));

    int t = threadIdx.x, wid = t >> 5, lane = t & 31;
    int wm = wid & 1, wn = wid >> 1;
    int m0 = blockIdx.y*128, n0 = blockIdx.x*128;
    int m0w = wm*64, n0w = wn*32;

    float acc[4][4][4];
    #pragma unroll
    for (int i = 0; i < 4; i++)
        #pragma unroll
        for (int j = 0; j < 4; j++)
            #pragma unroll
            for (int e = 0; e < 4; e++) acc[i][j][e] = 0.f;

    int laneRow = lane & 15, laneHi = lane >> 4;

    load_chunk<Kp>(sAb[0], sBb[0], A, B, m0, n0, 0, t);
    load_chunk<Kp>(sAb[1], sBb[1], A, B, m0, n0, 1, t);
    load_chunk<Kp>(sAb[2], sBb[2], A, B, m0, n0, 2, t);

    int bi = 0;
    for (int c = 0; c < KCH; c++) {
        int w = KCH - 1 - c;
        if (w >= 2)      asm volatile("cp.async.wait_group 2;" ::: "memory");
        else if (w == 1) asm volatile("cp.async.wait_group 1;" ::: "memory");
        else             asm volatile("cp.async.wait_group 0;" ::: "memory");
        __syncthreads();
        uint32_t curA = sAb[bi], curB = sBb[bi];

        #pragma unroll
        for (int ks = 0; ks < 4; ks++) {
            int seg = 2*ks + laneHi;
            uint32_t a[4][4], b[2][4];
            #pragma unroll
            for (int mi = 0; mi < 4; mi++) {
                int row = m0w + 16*mi + laneRow;
                ldm4(a[mi], curA + row*128 + (uint32_t)(seg ^ (row & 7))*16u);
            }
            #pragma unroll
            for (int nj = 0; nj < 2; nj++) {
                int row = n0w + 16*nj + laneRow;
                ldm4(b[nj], curB + row*128 + (uint32_t)(seg ^ (row & 7))*16u);
            }
            #pragma unroll
            for (int mi = 0; mi < 4; mi++)
                #pragma unroll
                for (int f = 0; f < 4; f++)
                    mma16816(acc[mi][f], a[mi], b[f>>1][f&1], b[f>>1][(f&1)+2]);
        }
        __syncthreads();
        if (c + 3 < KCH)
            load_chunk<Kp>(sAb[bi], sBb[bi], A, B, m0, n0, c + 3, t);
        if (++bi == 3) bi = 0;
    }

    // ---- epilogue: stage [n(128)][m(128)] fp32 with pad 130 ----
    {
        int q = lane & 3, r = lane >> 2;
        #pragma unroll
        for (int mi = 0; mi < 4; mi++) {
            int m_l = wm*64 + 16*mi + r;
            #pragma unroll
            for (int f = 0; f < 4; f++) {
                int n_l = wn*32 + 8*f + 2*q;
                stage[(size_t)n_l*130 + m_l]          = acc[mi][f][0];
                stage[(size_t)(n_l+1)*130 + m_l]      = acc[mi][f][1];
                stage[(size_t)n_l*130 + m_l + 8]      = acc[mi][f][2];
                stage[(size_t)(n_l+1)*130 + m_l + 8]  = acc[mi][f][3];
            }
        }
    }
    __syncthreads();

    // coalesced store: yT[(n0+n)*256 + m0 + m], bias added
    for (int idx = t; idx < 128*32; idx += 256) {
        int n_l = idx >> 5, m4 = idx & 31;
        float4 bb = __ldg((const float4*)&bias[m0 + m4*4]);
        float* sp = &stage[(size_t)n_l*130 + m4*4];
        float4 v;
        v.x = sp[0] + bb.x; v.y = sp[1] + bb.y;
        v.z = sp[2] + bb.z; v.w = sp[3] + bb.w;
        *(float4*)&yT[(size_t)(n0 + n_l)*256 + m0 + m4*4] = v;
    }

    // BN sums
    {
        int m_l = t & 127, nh = t >> 7;
        float bb = __ldg(&bias[m0 + m_l]);
        float s = 0.f, q = 0.f;
        #pragma unroll 4
        for (int j = 0; j < 64; j++) {
            float v = stage[(size_t)(nh*64 + j)*130 + m_l] + bb;
            s += v; q += v*v;
        }
        atomicAdd(&sacc[m0 + m_l], s);
        atomicAdd(&qacc[m0 + m_l], q);
    }
}

// ============================================================
// prep2: compute BN1 affine in-block, then relu(bn1(y1)) -> split bf16
// 8 channels/thread, uint4 stores
// ============================================================
__global__ void prep2(const float* __restrict__ g, const float* __restrict__ beta) {
    __shared__ float ssc[CMID], ssh[CMID];
    int t = threadIdx.x;
    {
        float mean = g_sum1[t] * (1.0f/(float)BNT);
        float var  = g_sq1[t]  * (1.0f/(float)BNT) - mean*mean;
        float r = rsqrtf(var + 1e-5f);
        float sc = g[t]*r;
        ssc[t] = sc;
        ssh[t] = beta[t] - mean*sc;
    }
    __syncthreads();
    int gi = blockIdx.x*256 + t;
    int n = gi >> 5, kg = gi & 31, k0 = kg*8;
    float v[8];
    #pragma unroll
    for (int h = 0; h < 2; h++) {
        float4 y = *(const float4*)&g_y1T[(size_t)n*CMID + k0 + h*4];
        int kb = k0 + h*4;
        v[h*4+0] = fmaxf(y.x*ssc[kb+0] + ssh[kb+0], 0.f);
        v[h*4+1] = fmaxf(y.y*ssc[kb+1] + ssh[kb+1], 0.f);
        v[h*4+2] = fmaxf(y.z*ssc[kb+2] + ssh[kb+2], 0.f);
        v[h*4+3] = fmaxf(y.w*ssc[kb+3] + ssh[kb+3], 0.f);
    }
    store_pack8((char*)g_y2B + (size_t)n*KP2*2 + (size_t)k0*6, v);
}

// ============================================================
// final: BN2 affine in-block, y2T [n][m] -> out [b][m][n] + ReLU
// ============================================================
__global__ void final_out(float* __restrict__ out,
                          const float* __restrict__ g, const float* __restrict__ beta) {
    __shared__ float tile[32][33];
    __shared__ float ssc[32], ssh[32];
    int b = blockIdx.z, m0 = blockIdx.y*32, n0 = blockIdx.x*32;
    int lx = threadIdx.x, ly = threadIdx.y;
    if (ly == 0) {
        int m = m0 + lx;
        float mean = g_sum2[m] * (1.0f/(float)BNT);
        float var  = g_sq2[m]  * (1.0f/(float)BNT) - mean*mean;
        float r = rsqrtf(var + 1e-5f);
        float sc = g[m]*r;
        ssc[lx] = sc;
        ssh[lx] = beta[m] - mean*sc;
    }
    #pragma unroll
    for (int i = ly; i < 32; i += 8)
        tile[i][lx] = g_y2T[(size_t)(b*NPTS + n0 + i)*COUT + m0 + lx];
    __syncthreads();
    #pragma unroll
    for (int i = ly; i < 32; i += 8) {
        float v = tile[lx][i]*ssc[i] + ssh[i];
        out[((size_t)b*COUT + m0 + i)*NPTS + n0 + lx] = fmaxf(v, 0.f);
    }
}

// ============================================================
extern "C" void kernel_launch(void* const* d_in, const int* in_sizes, int n_in,
                              void* d_out, int out_size) {
    const float* pos1 = (const float*)d_in[0];
    const float* pos2 = (const float*)d_in[1];
    const float* f1   = (const float*)d_in[2];
    const float* f2   = (const float*)d_in[3];
    const float* W1   = (const float*)d_in[4];
    const float* b1   = (const float*)d_in[5];
    const float* g1   = (const float*)d_in[6];
    const float* be1  = (const float*)d_in[7];
    const float* W2   = (const float*)d_in[8];
    const float* b2   = (const float*)d_in[9];
    const float* g2   = (const float*)d_in[10];
    const float* be2  = (const float*)d_in[11];
    float* out = (float*)d_out;

    cudaFuncSetAttribute(mma_gemm<0>, cudaFuncAttributeMaxDynamicSharedMemorySize, SMEM_DYN);
    cudaFuncSetAttribute(mma_gemm<1>, cudaFuncAttributeMaxDynamicSharedMemorySize, SMEM_DYN);

    knn_kernel   <<<dim3(NPTS/256, BB), 256>>>(pos1, pos2);
    transpose_f2 <<<dim3(SPTS/32, D2C/32, BB), dim3(32,8)>>>(f2);
    interp_kernel<<<BNT/8, 256>>>();
    copy_f1      <<<dim3(NPTS/32, D1C/64, BB), 256>>>(f1);
    wexpand_all  <<<(CMID*CIN + COUT*CMID)/256, 256>>>(W1, W2);

    mma_gemm<0>  <<<dim3(BNT/128, 2), 256, SMEM_DYN>>>(b1);
    prep2        <<<(BNT*32)/256, 256>>>(g1, be1);
    mma_gemm<1>  <<<dim3(BNT/128, 2), 256, SMEM_DYN>>>(b2);
    final_out    <<<dim3(NPTS/32, COUT/32, BB), dim3(32,8)>>>(out, g2, be2);
}

// round 11
// speedup vs baseline: 1.9104x; 1.0323x over previous
#include <cuda_runtime.h>
#include <cuda_bf16.h>
#include <math.h>
#include <stdint.h>

#define BB    4
#define NPTS  8192
#define SPTS  2048
#define D1C   128
#define D2C   256
#define CIN   384
#define CMID  256
#define COUT  256
#define BNT   (BB*NPTS)     // 32768
#define KP1   (3*CIN)       // 1152
#define KP2   (3*CMID)      // 768
#define KCH1  (KP1/64)      // 18 chunks of 64
#define KCH2  (KP2/64)      // 12

// ---------------- scratch (device globals) ----------------
__device__ __align__(256) float          g_f2t[BB*SPTS*D2C];          // [B,S,D2]
__device__ __align__(256) __nv_bfloat16  g_featB[(size_t)BNT*KP1];    // B op GEMM1, point-major
__device__ __align__(256) __nv_bfloat16  g_W1e[CMID*KP1];             // A op GEMM1
__device__ __align__(256) __nv_bfloat16  g_W2e[COUT*KP2];             // A op GEMM2
__device__ __align__(256) float          g_y1T[(size_t)BNT*CMID];     // y1 pre-BN, point-major
__device__ __align__(256) __nv_bfloat16  g_y2B[(size_t)BNT*KP2];      // B op GEMM2
__device__ __align__(256) float          g_y2T[(size_t)BNT*COUT];     // y2 pre-BN, point-major
__device__ int   g_idx[BNT*3];
__device__ float g_w[BNT*3];
__device__ float g_sum1[CMID], g_sq1[CMID], g_sum2[COUT], g_sq2[COUT];

// ---------------- small helpers ----------------
__device__ __forceinline__ void cp16(uint32_t dst, const void* src){
    asm volatile("cp.async.cg.shared.global [%0], [%1], 16;" :: "r"(dst), "l"(src));
}
__device__ __forceinline__ void ldm4(uint32_t* r, uint32_t addr){
    asm volatile("ldmatrix.sync.aligned.m8n8.x4.shared.b16 {%0,%1,%2,%3}, [%4];"
        : "=r"(r[0]), "=r"(r[1]), "=r"(r[2]), "=r"(r[3]) : "r"(addr));
}
__device__ __forceinline__ void mma16816(float* d, const uint32_t* a, uint32_t b0, uint32_t b1){
    asm volatile(
        "mma.sync.aligned.m16n8k16.row.col.f32.bf16.bf16.f32 "
        "{%0,%1,%2,%3}, {%4,%5,%6,%7}, {%8,%9}, {%0,%1,%2,%3};"
        : "+f"(d[0]), "+f"(d[1]), "+f"(d[2]), "+f"(d[3])
        : "r"(a[0]), "r"(a[1]), "r"(a[2]), "r"(a[3]), "r"(b0), "r"(b1));
}

__device__ __forceinline__ void split_bf(float v, uint32_t& hi, uint32_t& lo){
    __nv_bfloat16 h = __float2bfloat16(v);
    float r = v - __bfloat162float(h);
    __nv_bfloat16 l = __float2bfloat16(r);
    hi = (uint32_t)__bfloat16_as_ushort(h);
    lo = (uint32_t)__bfloat16_as_ushort(l);
}

// B-side pattern per channel: [hi, lo, hi]; packs 4 channels -> 6 uint32
__device__ __forceinline__ void packB4(const float* v, uint32_t* u){
    uint32_t h[4], l[4];
    #pragma unroll
    for (int j = 0; j < 4; j++) split_bf(v[j], h[j], l[j]);
    u[0] = h[0] | (l[0] << 16);
    u[1] = h[0] | (h[1] << 16);
    u[2] = l[1] | (h[1] << 16);
    u[3] = h[2] | (l[2] << 16);
    u[4] = h[2] | (h[3] << 16);
    u[5] = l[3] | (h[3] << 16);
}

// 8 channels -> 3 x uint4 (48 bytes, 16B-aligned when k0 % 8 == 0)
__device__ __forceinline__ void store_pack8(void* dst, const float* v){
    uint32_t u[12];
    packB4(v, u); packB4(v + 4, u + 6);
    uint4* d4 = (uint4*)dst;
    d4[0] = make_uint4(u[0], u[1], u[2],  u[3]);
    d4[1] = make_uint4(u[4], u[5], u[6],  u[7]);
    d4[2] = make_uint4(u[8], u[9], u[10], u[11]);
}

// ============================================================
// 3-NN (block (0,0) also zeroes BN accumulators)
// ============================================================
__global__ void knn_kernel(const float* __restrict__ pos1,
                           const float* __restrict__ pos2) {
    __shared__ float4 sp[SPTS];
    int b = blockIdx.y;
    if (blockIdx.x == 0 && blockIdx.y == 0) {
        int t = threadIdx.x;
        g_sum1[t] = 0.f; g_sq1[t] = 0.f; g_sum2[t] = 0.f; g_sq2[t] = 0.f;
    }
    const float* p2 = pos2 + (size_t)b*3*SPTS;
    for (int s = threadIdx.x; s < SPTS; s += blockDim.x) {
        float x = p2[s], y = p2[SPTS+s], z = p2[2*SPTS+s];
        sp[s] = make_float4(x, y, z, x*x+y*y+z*z);
    }
    __syncthreads();

    int n = blockIdx.x*blockDim.x + threadIdx.x;
    const float* p1 = pos1 + (size_t)b*3*NPTS;
    float px = p1[n], py = p1[NPTS+n], pz = p1[2*NPTS+n];
    float n1 = px*px+py*py+pz*pz;

    float d0v=1e30f, d1v=1e30f, d2v=1e30f;
    int   i0=0, i1=0, i2=0;
    #pragma unroll 4
    for (int s = 0; s < SPTS; s++) {
        float4 c = sp[s];
        float d = n1 - 2.0f*(px*c.x + py*c.y + pz*c.z) + c.w;
        if (d < d2v) {
            if (d < d1v) {
                d2v = d1v; i2 = i1;
                if (d < d0v) { d1v = d0v; i1 = i0; d0v = d; i0 = s; }
                else         { d1v = d;   i1 = s; }
            } else { d2v = d; i2 = s; }
        }
    }
    float a0 = fmaxf(d0v, 1e-10f), a1 = fmaxf(d1v, 1e-10f), a2 = fmaxf(d2v, 1e-10f);
    float w0 = 1.0f/a0, w1 = 1.0f/a1, w2 = 1.0f/a2;
    float inv = 1.0f/(w0+w1+w2);
    int base = (b*NPTS + n)*3;
    g_idx[base+0]=i0; g_idx[base+1]=i1; g_idx[base+2]=i2;
    g_w[base+0]=w0*inv; g_w[base+1]=w1*inv; g_w[base+2]=w2*inv;
}

// ============================================================
// feature2 [B,D2,S] -> g_f2t [B,S,D2]
// ============================================================
__global__ void transpose_f2(const float* __restrict__ f2) {
    __shared__ float t[32][33];
    int b = blockIdx.z;
    int d0 = blockIdx.y*32, s0 = blockIdx.x*32;
    int lx = threadIdx.x, ly = threadIdx.y;
    const float* src = f2 + (size_t)b*D2C*SPTS;
    #pragma unroll
    for (int i = ly; i < 32; i += 8)
        t[i][lx] = src[(size_t)(d0+i)*SPTS + s0 + lx];
    __syncthreads();
    float* dst = g_f2t + (size_t)b*SPTS*D2C;
    #pragma unroll
    for (int i = ly; i < 32; i += 8)
        dst[(size_t)(s0+i)*D2C + d0 + lx] = t[lx][i];
}

// ============================================================
// interp: weighted 3-NN -> g_featB rows k'=[0, 3*D2)
// block = 8 points x 32 threads (8 channels/thread, uint4 stores)
// ============================================================
__global__ void interp_kernel() {
    int t = threadIdx.x;
    int p = blockIdx.x*8 + (t >> 5);
    int kg = t & 31;
    int i0 = __ldg(&g_idx[p*3+0]), i1 = __ldg(&g_idx[p*3+1]), i2 = __ldg(&g_idx[p*3+2]);
    float w0 = __ldg(&g_w[p*3+0]), w1 = __ldg(&g_w[p*3+1]), w2 = __ldg(&g_w[p*3+2]);
    int b = p >> 13;
    const float* f2 = g_f2t + (size_t)b*SPTS*D2C;
    int k0 = kg*8;
    float v[8];
    #pragma unroll
    for (int h = 0; h < 2; h++) {
        float4 a = *(const float4*)&f2[(size_t)i0*D2C + k0 + h*4];
        float4 c = *(const float4*)&f2[(size_t)i1*D2C + k0 + h*4];
        float4 d = *(const float4*)&f2[(size_t)i2*D2C + k0 + h*4];
        v[h*4+0] = w0*a.x + w1*c.x + w2*d.x;
        v[h*4+1] = w0*a.y + w1*c.y + w2*d.y;
        v[h*4+2] = w0*a.z + w1*c.z + w2*d.z;
        v[h*4+3] = w0*a.w + w1*c.w + w2*d.w;
    }
    store_pack8((char*)g_featB + (size_t)p*KP1*2 + (size_t)k0*6, v);
}

// ============================================================
// feature1 [B,D1,N] -> g_featB rows k'=[3*D2, 3*CIN)
// ============================================================
__global__ void copy_f1(const float* __restrict__ f1) {
    __shared__ float tile[64][33];
    int b = blockIdx.z, d0 = blockIdx.y*64, n0 = blockIdx.x*32;
    int t = threadIdx.x;
    int lx = t & 31, ly = t >> 5;
    const float* src = f1 + ((size_t)b*D1C + d0)*NPTS + n0;
    #pragma unroll
    for (int i = ly; i < 64; i += 8)
        tile[i][lx] = src[(size_t)i*NPTS + lx];
    __syncthreads();
    int g = t & 7, nn = t >> 3;
    int n = b*NPTS + n0 + nn;
    int d = d0 + g*8;
    float v[8];
    #pragma unroll
    for (int j = 0; j < 8; j++) v[j] = tile[g*8+j][nn];
    store_pack8((char*)g_featB + (size_t)n*KP1*2 + (size_t)(D2C + d)*6, v);
}

// ============================================================
// weight expand (both layers): A pattern [hi, hi, lo]
// ============================================================
__global__ void wexpand_all(const float* __restrict__ W1,
                            const float* __restrict__ W2) {
    int i = blockIdx.x*blockDim.x + threadIdx.x;
    float v; __nv_bfloat16* p;
    if (i < CMID*CIN) {
        int m = i / CIN, k = i - m*CIN;
        v = W1[i];
        p = g_W1e + (size_t)m*KP1 + 3*k;
    } else {
        int j = i - CMID*CIN;
        int m = j / CMID, k = j - m*CMID;
        v = W2[j];
        p = g_W2e + (size_t)m*KP2 + 3*k;
    }
    uint32_t hi, lo; split_bf(v, hi, lo);
    p[0] = __ushort_as_bfloat16((unsigned short)hi);
    p[1] = __ushort_as_bfloat16((unsigned short)hi);
    p[2] = __ushort_as_bfloat16((unsigned short)lo);
}

// ============================================================
// mma.sync GEMM: CTA 256m x 128n x 64k (FULL M per CTA -> B read once).
// 8 warps (4m x 2n), warp tile 64x64. 4-stage cp.async pipeline,
// single __syncthreads per chunk.
// Epilogue: smem stage (pad 260), contiguous point-major store, BN atomics.
// ============================================================
#define STAGE_BYTES 49152            // A 32KB + B 16KB
#define SMEM_DYN    (4*STAGE_BYTES + 128)

template<int Kp>
__device__ __forceinline__ void load_chunk(uint32_t sA, uint32_t sB,
        const __nv_bfloat16* __restrict__ A, const __nv_bfloat16* __restrict__ B,
        int n0, int c, int t) {
    int seg = t & 7, r0 = t >> 3;   // r0 in 0..31
    const char* Ab = (const char*)A + ((size_t)c*64)*2 + (size_t)seg*16;
    const char* Bb = (const char*)B + ((size_t)n0*Kp + c*64)*2 + (size_t)seg*16;
    #pragma unroll
    for (int i = 0; i < 8; i++) {    // A: 256 rows
        int row = r0 + i*32;
        uint32_t sw = (uint32_t)(seg ^ (row & 7))*16u;
        cp16(sA + row*128 + sw, Ab + (size_t)row*Kp*2);
    }
    #pragma unroll
    for (int i = 0; i < 4; i++) {    // B: 128 rows
        int row = r0 + i*32;
        uint32_t sw = (uint32_t)(seg ^ (row & 7))*16u;
        cp16(sB + row*128 + sw, Bb + (size_t)row*Kp*2);
    }
    asm volatile("cp.async.commit_group;" ::: "memory");
}

template<int MODE>
__global__ void __launch_bounds__(256)
mma_gemm(const float* __restrict__ bias) {
    constexpr int KCH = (MODE == 0) ? KCH1 : KCH2;
    constexpr int Kp  = KCH*64;
    const __nv_bfloat16* A = (MODE == 0) ? g_W1e  : g_W2e;
    const __nv_bfloat16* B = (MODE == 0) ? g_featB : g_y2B;
    float* yT   = (MODE == 0) ? g_y1T : g_y2T;
    float* sacc = (MODE == 0) ? g_sum1 : g_sum2;
    float* qacc = (MODE == 0) ? g_sq1  : g_sq2;

    extern __shared__ char smem[];
    uint32_t sb;
    asm("{ .reg .u64 t; cvta.to.shared.u64 t, %1; cvt.u32.u64 %0, t; }"
        : "=r"(sb) : "l"(smem));
    uint32_t base = (sb + 127u) & ~127u;
    float* stage = (float*)(smem + (base - sb));

    int t = threadIdx.x, wid = t >> 5, lane = t & 31;
    int wm = wid >> 1, wn = wid & 1;      // 4 x 2 warp grid
    int n0 = blockIdx.x*128;
    int m0w = wm*64, n0w = wn*64;

    float acc[4][8][4];
    #pragma unroll
    for (int i = 0; i < 4; i++)
        #pragma unroll
        for (int j = 0; j < 8; j++)
            #pragma unroll
            for (int e = 0; e < 4; e++) acc[i][j][e] = 0.f;

    int laneRow = lane & 15, laneHi = lane >> 4;

    load_chunk<Kp>(base + 0*STAGE_BYTES, base + 0*STAGE_BYTES + 32768, A, B, n0, 0, t);
    load_chunk<Kp>(base + 1*STAGE_BYTES, base + 1*STAGE_BYTES + 32768, A, B, n0, 1, t);
    load_chunk<Kp>(base + 2*STAGE_BYTES, base + 2*STAGE_BYTES + 32768, A, B, n0, 2, t);

    int bi = 0;
    for (int c = 0; c < KCH; c++) {
        int w = KCH - 1 - c;
        if (w >= 2)      asm volatile("cp.async.wait_group 2;" ::: "memory");
        else if (w == 1) asm volatile("cp.async.wait_group 1;" ::: "memory");
        else             asm volatile("cp.async.wait_group 0;" ::: "memory");
        __syncthreads();
        uint32_t curA = base + bi*STAGE_BYTES;
        uint32_t curB = curA + 32768;

        #pragma unroll
        for (int ks = 0; ks < 4; ks++) {
            int seg = 2*ks + laneHi;
            uint32_t a[4][4], b[4][4];
            #pragma unroll
            for (int mi = 0; mi < 4; mi++) {
                int row = m0w + 16*mi + laneRow;
                ldm4(a[mi], curA + row*128 + (uint32_t)(seg ^ (row & 7))*16u);
            }
            #pragma unroll
            for (int nj = 0; nj < 4; nj++) {
                int row = n0w + 16*nj + laneRow;
                ldm4(b[nj], curB + row*128 + (uint32_t)(seg ^ (row & 7))*16u);
            }
            #pragma unroll
            for (int mi = 0; mi < 4; mi++)
                #pragma unroll
                for (int f = 0; f < 8; f++)
                    mma16816(acc[mi][f], a[mi], b[f>>1][f&1], b[f>>1][(f&1)+2]);
        }
        // load chunk c+3 into the slot consumed at iteration c-1:
        // the __syncthreads at the top of this iteration ordered those reads.
        if (c + 3 < KCH) {
            uint32_t nb = base + ((bi + 3) & 3)*STAGE_BYTES;
            load_chunk<Kp>(nb, nb + 32768, A, B, n0, c + 3, t);
        }
        bi = (bi + 1) & 3;
    }
    __syncthreads();   // operand smem -> stage reuse

    // ---- epilogue: stage [n(128)][m(256)] fp32, pad 260 ----
    {
        int q = lane & 3, r = lane >> 2;
        #pragma unroll
        for (int mi = 0; mi < 4; mi++) {
            int m_l = m0w + 16*mi + r;
            #pragma unroll
            for (int f = 0; f < 8; f++) {
                int n_l = n0w + 8*f + 2*q;
                stage[(size_t)n_l*260 + m_l]          = acc[mi][f][0];
                stage[(size_t)(n_l+1)*260 + m_l]      = acc[mi][f][1];
                stage[(size_t)n_l*260 + m_l + 8]      = acc[mi][f][2];
                stage[(size_t)(n_l+1)*260 + m_l + 8]  = acc[mi][f][3];
            }
        }
    }
    __syncthreads();

    // contiguous store: yT[(n0+n)*256 + m], bias added (m spans full 0..255)
    #pragma unroll 4
    for (int idx = t; idx < 128*64; idx += 256) {
        int n_l = idx >> 6, m4 = idx & 63;
        float4 bb = __ldg((const float4*)&bias[m4*4]);
        float* sp = &stage[(size_t)n_l*260 + m4*4];
        float4 v;
        v.x = sp[0] + bb.x; v.y = sp[1] + bb.y;
        v.z = sp[2] + bb.z; v.w = sp[3] + bb.w;
        *(float4*)&yT[(size_t)(n0 + n_l)*256 + m4*4] = v;
    }

    // BN sums: thread t = channel t, reduce over 128 points
    {
        float bb = __ldg(&bias[t]);
        float s = 0.f, q = 0.f;
        #pragma unroll 4
        for (int j = 0; j < 128; j++) {
            float v = stage[(size_t)j*260 + t] + bb;
            s += v; q += v*v;
        }
        atomicAdd(&sacc[t], s);
        atomicAdd(&qacc[t], q);
    }
}

// ============================================================
// prep2: BN1 affine in-block, relu(bn1(y1)) -> split bf16 B operand
// ============================================================
__global__ void prep2(const float* __restrict__ g, const float* __restrict__ beta) {
    __shared__ float ssc[CMID], ssh[CMID];
    int t = threadIdx.x;
    {
        float mean = g_sum1[t] * (1.0f/(float)BNT);
        float var  = g_sq1[t]  * (1.0f/(float)BNT) - mean*mean;
        float r = rsqrtf(var + 1e-5f);
        float sc = g[t]*r;
        ssc[t] = sc;
        ssh[t] = beta[t] - mean*sc;
    }
    __syncthreads();
    int gi = blockIdx.x*256 + t;
    int n = gi >> 5, kg = gi & 31, k0 = kg*8;
    float v[8];
    #pragma unroll
    for (int h = 0; h < 2; h++) {
        float4 y = *(const float4*)&g_y1T[(size_t)n*CMID + k0 + h*4];
        int kb = k0 + h*4;
        v[h*4+0] = fmaxf(y.x*ssc[kb+0] + ssh[kb+0], 0.f);
        v[h*4+1] = fmaxf(y.y*ssc[kb+1] + ssh[kb+1], 0.f);
        v[h*4+2] = fmaxf(y.z*ssc[kb+2] + ssh[kb+2], 0.f);
        v[h*4+3] = fmaxf(y.w*ssc[kb+3] + ssh[kb+3], 0.f);
    }
    store_pack8((char*)g_y2B + (size_t)n*KP2*2 + (size_t)k0*6, v);
}

// ============================================================
// final: BN2 affine in-block, y2T [n][m] -> out [b][m][n] + ReLU
// ============================================================
__global__ void final_out(float* __restrict__ out,
                          const float* __restrict__ g, const float* __restrict__ beta) {
    __shared__ float tile[32][33];
    __shared__ float ssc[32], ssh[32];
    int b = blockIdx.z, m0 = blockIdx.y*32, n0 = blockIdx.x*32;
    int lx = threadIdx.x, ly = threadIdx.y;
    if (ly == 0) {
        int m = m0 + lx;
        float mean = g_sum2[m] * (1.0f/(float)BNT);
        float var  = g_sq2[m]  * (1.0f/(float)BNT) - mean*mean;
        float r = rsqrtf(var + 1e-5f);
        float sc = g[m]*r;
        ssc[lx] = sc;
        ssh[lx] = beta[m] - mean*sc;
    }
    #pragma unroll
    for (int i = ly; i < 32; i += 8)
        tile[i][lx] = g_y2T[(size_t)(b*NPTS + n0 + i)*COUT + m0 + lx];
    __syncthreads();
    #pragma unroll
    for (int i = ly; i < 32; i += 8) {
        float v = tile[lx][i]*ssc[i] + ssh[i];
        out[((size_t)b*COUT + m0 + i)*NPTS + n0 + lx] = fmaxf(v, 0.f);
    }
}

// ============================================================
extern "C" void kernel_launch(void* const* d_in, const int* in_sizes, int n_in,
                              void* d_out, int out_size) {
    const float* pos1 = (const float*)d_in[0];
    const float* pos2 = (const float*)d_in[1];
    const float* f1   = (const float*)d_in[2];
    const float* f2   = (const float*)d_in[3];
    const float* W1   = (const float*)d_in[4];
    const float* b1   = (const float*)d_in[5];
    const float* g1   = (const float*)d_in[6];
    const float* be1  = (const float*)d_in[7];
    const float* W2   = (const float*)d_in[8];
    const float* b2   = (const float*)d_in[9];
    const float* g2   = (const float*)d_in[10];
    const float* be2  = (const float*)d_in[11];
    float* out = (float*)d_out;

    cudaFuncSetAttribute(mma_gemm<0>, cudaFuncAttributeMaxDynamicSharedMemorySize, SMEM_DYN);
    cudaFuncSetAttribute(mma_gemm<1>, cudaFuncAttributeMaxDynamicSharedMemorySize, SMEM_DYN);

    knn_kernel   <<<dim3(NPTS/256, BB), 256>>>(pos1, pos2);
    transpose_f2 <<<dim3(SPTS/32, D2C/32, BB), dim3(32,8)>>>(f2);
    interp_kernel<<<BNT/8, 256>>>();
    copy_f1      <<<dim3(NPTS/32, D1C/64, BB), 256>>>(f1);
    wexpand_all  <<<(CMID*CIN + COUT*CMID)/256, 256>>>(W1, W2);

    mma_gemm<0>  <<<BNT/128, 256, SMEM_DYN>>>(b1);
    prep2        <<<(BNT*32)/256, 256>>>(g1, be1);
    mma_gemm<1>  <<<BNT/128, 256, SMEM_DYN>>>(b2);
    final_out    <<<dim3(NPTS/32, COUT/32, BB), dim3(32,8)>>>(out, g2, be2);
}